// round 10
// baseline (speedup 1.0000x reference)
#include <cuda_runtime.h>
#include <cstdint>

// C4ByteNibbleVM — integer semantics of the one-hot "neural VM":
//   s = a + b (u32, little-endian ripple carry), out_byte[i] = s_byte[i] ^ a_byte[i],
// output as exact one-hot [B,4,256] f32 (reference softmax is one-hot to ~1e-7).
//
// R8 -> R9: identical probe structure (4-stage x 256B early-exit, paired-row
// float4 loads, FFMA+REDUX decode), but each warp handles TWO consecutive
// words SEQUENTIALLY (only word 0's 32-bit result persists across word 1's
// probe) and then emits both words' outputs as one contiguous 2KB store burst.
// Goal: longer DRAM read bursts and batched writes -> fewer bus turnarounds.

__global__ __launch_bounds__(256, 6) void c4_vm_kernel(
    const float* __restrict__ a,
    const float* __restrict__ b,
    float* __restrict__ out,
    int nwords)
{
    const int warp = (blockIdx.x * (blockDim.x >> 5)) + (threadIdx.x >> 5);
    const int lane = threadIdx.x & 31;
    const int w0 = warp * 2;
    if (w0 >= nwords) return;
    const bool has2 = (w0 + 1) < nwords;

    const int hl = lane >> 4;                   // which row of the pair this lane probes
    const int lr = lane & 15;                   // float4 slot within the 256B chunk
    const int hsh = hl << 4;                    // 0 or 16: packing shift

    // Position weights (+1 so 0 means "no hit"): chunk-local index of v.x..v.w
    const float f0 = (float)(lr * 4 + 1);
    const float f1 = f0 + 1.0f, f2 = f0 + 2.0f, f3 = f0 + 3.0f;

    unsigned oa[2];

#pragma unroll
    for (int t = 0; t < 2; t++) {
        const int w = w0 + t;
        if (t == 1 && !has2) { oa[1] = 0; break; }

        // Row = 64 float4; word block = 4 rows = 256 float4 per side.
        const float4* __restrict__ a4 =
            reinterpret_cast<const float4*>(a) + (size_t)w * 256;
        const float4* __restrict__ b4 =
            reinterpret_cast<const float4*>(b) + (size_t)w * 256;

        unsigned av = 0, bv = 0;
        unsigned unres = 0xffu;                 // bit gr: row gr (0-3 a, 4-7 b) unresolved

#pragma unroll
        for (int s = 0; s < 4; s++) {           // stage s: floats [s*64, s*64+64)
            if (unres) {                        // warp-uniform
                float4 v[4];
#pragma unroll
                for (int p = 0; p < 4; p++) {
                    const int rp = (p & 1) * 2 + hl;
                    const int gr = (p >> 1) * 4 + rp;
                    v[p] = make_float4(0.f, 0.f, 0.f, 0.f);
                    if ((unres >> gr) & 1u) {   // per-lane predicate
                        const float4* base = (p < 2) ? a4 : b4;
                        v[p] = __ldcs(base + rp * 64 + s * 16 + lr);
                    }
                }
#pragma unroll
                for (int p = 0; p < 4; p++) {
                    const float4 vv = v[p];
                    const float loc =
                        fmaf(vv.x, f0, fmaf(vv.y, f1, fmaf(vv.z, f2, vv.w * f3)));
                    const unsigned li = ((unsigned)(int)loc) << hsh;
                    const unsigned tt = __reduce_add_sync(0xffffffffu, li);
#pragma unroll
                    for (int h = 0; h < 2; h++) {
                        const int rp2 = (p & 1) * 2 + h;
                        const int gr2 = (p >> 1) * 4 + rp2;
                        if ((unres >> gr2) & 1u) {          // warp-uniform
                            const unsigned tp = (tt >> (16 * h)) & 0xffffu;
                            if (tp) {                       // warp-uniform
                                const unsigned pos = s * 64 + tp - 1;
                                if (p < 2) av |= pos << (8 * rp2);
                                else       bv |= pos << (8 * rp2);
                                unres &= ~(1u << gr2);
                            }
                        }
                    }
                }
            }
        }
        oa[t] = (av + bv) ^ av;                 // integer VM op for word t
    }

    // ---- Batched one-hot output: 2 words x 4 rows = contiguous 2KB burst ----
#pragma unroll
    for (int t = 0; t < 2; t++) {
        if (t == 1 && !has2) break;
        const unsigned o = oa[t];
        float4* __restrict__ o4 =
            reinterpret_cast<float4*>(out) + (size_t)(w0 + t) * 256;
#pragma unroll
        for (int i = 0; i < 4; i++) {
            const unsigned ob = (o >> (8 * i)) & 0xffu;
            const int q = ob >> 2;              // which float4 (0..63)
            const int e = ob & 3;               // element within float4
            float4 z0 = make_float4(0.f, 0.f, 0.f, 0.f);
            float4 z1 = make_float4(0.f, 0.f, 0.f, 0.f);
            if (q == lane)      (&z0.x)[e] = 1.0f;
            if (q == lane + 32) (&z1.x)[e] = 1.0f;
            __stcs(&o4[i * 64 + lane], z0);
            __stcs(&o4[i * 64 + 32 + lane], z1);
        }
    }
}

extern "C" void kernel_launch(void* const* d_in, const int* in_sizes, int n_in,
                              void* d_out, int out_size)
{
    const float* a = (const float*)d_in[0];   // a_bytes [B,4,256]
    const float* b = (const float*)d_in[1];   // b_bytes [B,4,256]
    float* out = (float*)d_out;               // [B,4,256]

    const int nwords = in_sizes[0] / 1024;    // B
    const int words_per_block = 16;           // 8 warps x 2 words
    const int blocks = (nwords + words_per_block - 1) / words_per_block;

    c4_vm_kernel<<<blocks, 256>>>(a, b, out, nwords);
}

// round 11
// speedup vs baseline: 1.0401x; 1.0401x over previous
#include <cuda_runtime.h>
#include <cstdint>

// C4ByteNibbleVM — integer semantics of the one-hot "neural VM":
//   s = a + b (u32, little-endian ripple carry), out_byte[i] = s_byte[i] ^ a_byte[i],
// output as exact one-hot [B,4,256] f32 (reference softmax is one-hot to ~1e-7).
//
// R9 -> R10: revert to the R8 single-word kernel (best kernel time, natural
// register demand exactly 36) and raise the occupancy bound to 7 blocks/SM.
// 36 regs is precisely the 7-block cap (65536/1792), so this is free occupancy
// (+17% resident warps) with no spill — targeted at the thin late probe epochs
// that keep DRAM% at 78 instead of R1's 85.

__global__ __launch_bounds__(256, 7) void c4_vm_kernel(
    const float* __restrict__ a,
    const float* __restrict__ b,
    float* __restrict__ out,
    int nwords)
{
    const int warp = (blockIdx.x * (blockDim.x >> 5)) + (threadIdx.x >> 5);
    const int lane = threadIdx.x & 31;
    if (warp >= nwords) return;

    const int hl = lane >> 4;                   // which row of the pair this lane probes
    const int lr = lane & 15;                   // float4 slot within the 256B chunk
    const int hsh = hl << 4;                    // 0 or 16: packing shift

    // Position weights (+1 so 0 means "no hit"): chunk-local index of v.x..v.w
    const float f0 = (float)(lr * 4 + 1);
    const float f1 = f0 + 1.0f, f2 = f0 + 2.0f, f3 = f0 + 3.0f;

    // Row = 64 float4; word block = 4 rows = 256 float4 per side.
    const float4* __restrict__ a4 = reinterpret_cast<const float4*>(a) + (size_t)warp * 256;
    const float4* __restrict__ b4 = reinterpret_cast<const float4*>(b) + (size_t)warp * 256;

    unsigned av = 0, bv = 0;
    unsigned unres = 0xffu;                     // bit gr: row gr (0-3 = a, 4-7 = b) unresolved

#pragma unroll
    for (int s = 0; s < 4; s++) {               // stage s covers floats [s*64, s*64+64)
        if (unres) {                            // warp-uniform
            float4 v[4];
            // ---- 4 paired loads: pair p covers rows {(p&1)*2 + hl} of side p>>1 ----
#pragma unroll
            for (int p = 0; p < 4; p++) {
                const int rp = (p & 1) * 2 + hl;        // row within side (lane-dependent)
                const int gr = (p >> 1) * 4 + rp;       // global row bit
                v[p] = make_float4(0.f, 0.f, 0.f, 0.f);
                if ((unres >> gr) & 1u) {               // per-lane predicate
                    const float4* base = (p < 2) ? a4 : b4;
                    v[p] = __ldcs(base + rp * 64 + s * 16 + lr);
                }
            }
            // ---- decode: FFMA dot + f2i + one packed REDUX per pair ----
#pragma unroll
            for (int p = 0; p < 4; p++) {
                const float4 vv = v[p];
                const float loc =
                    fmaf(vv.x, f0, fmaf(vv.y, f1, fmaf(vv.z, f2, vv.w * f3)));
                const unsigned li = ((unsigned)(int)loc) << hsh;
                const unsigned t = __reduce_add_sync(0xffffffffu, li);
#pragma unroll
                for (int h = 0; h < 2; h++) {
                    const int rp2 = (p & 1) * 2 + h;
                    const int gr2 = (p >> 1) * 4 + rp2;
                    if ((unres >> gr2) & 1u) {          // warp-uniform
                        const unsigned tp = (t >> (16 * h)) & 0xffffu;
                        if (tp) {                       // warp-uniform
                            const unsigned pos = s * 64 + tp - 1;
                            if (p < 2) av |= pos << (8 * rp2);
                            else       bv |= pos << (8 * rp2);
                            unres &= ~(1u << gr2);
                        }
                    }
                }
            }
        }
    }

    // ---- Integer VM op ----
    const unsigned o = (av + bv) ^ av;

    // ---- One-hot output: 4 rows x 1KB, coalesced streaming 128-bit stores ----
    float4* __restrict__ o4 = reinterpret_cast<float4*>(out) + (size_t)warp * 256;

#pragma unroll
    for (int i = 0; i < 4; i++) {
        const unsigned ob = (o >> (8 * i)) & 0xffu;
        const int q = ob >> 2;                  // which float4 (0..63)
        const int e = ob & 3;                   // element within float4
        float4 z0 = make_float4(0.f, 0.f, 0.f, 0.f);
        float4 z1 = make_float4(0.f, 0.f, 0.f, 0.f);
        if (q == lane)      (&z0.x)[e] = 1.0f;
        if (q == lane + 32) (&z1.x)[e] = 1.0f;
        __stcs(&o4[i * 64 + lane], z0);
        __stcs(&o4[i * 64 + 32 + lane], z1);
    }
}

extern "C" void kernel_launch(void* const* d_in, const int* in_sizes, int n_in,
                              void* d_out, int out_size)
{
    const float* a = (const float*)d_in[0];   // a_bytes [B,4,256]
    const float* b = (const float*)d_in[1];   // b_bytes [B,4,256]
    float* out = (float*)d_out;               // [B,4,256]

    const int nwords = in_sizes[0] / 1024;    // B
    const int warps_per_block = 8;            // 256 threads
    const int blocks = (nwords + warps_per_block - 1) / warps_per_block;

    c4_vm_kernel<<<blocks, 256>>>(a, b, out, nwords);
}